// round 1
// baseline (speedup 1.0000x reference)
#include <cuda_runtime.h>
#include <math.h>

// Problem constants (fixed by the reference)
#define BATCH 4
#define SEQ   2048
#define DIM   1024

// SGEMM tiling
#define BM 128
#define BN 128
#define BK 16
#define TM 8
#define TN 8
#define NTHREADS 256   // (BM/TM)*(BN/TN)

// Scratch (device globals: allocation-free per harness rules)
__device__ float g_Q[BATCH * SEQ * DIM];
__device__ float g_K[BATCH * SEQ * DIM];
__device__ float g_V[BATCH * SEQ * DIM];
__device__ float g_S[(size_t)BATCH * SEQ * SEQ];

// ---------------------------------------------------------------------------
// Tiled SGEMM: C = alpha * A * op(B)
//   A: [M, K] row-major
//   B: TRANSB ? [N, K] row-major (C[i,j] = sum_k A[i,k] * B[j,k])
//            : [K, N] row-major
//   C: [M, N] row-major
// CSKIP: skip blocks fully above the causal diagonal (only valid when M==N
//        semantics are query-row x key-col, used for S = Q K^T).
// ---------------------------------------------------------------------------
template <bool TRANSB, bool CSKIP>
__global__ __launch_bounds__(NTHREADS)
void sgemm_kernel(const float* __restrict__ A,
                  const float* __restrict__ Bmat,
                  float* __restrict__ C,
                  int M, int N, int K, float alpha,
                  long strideA, long strideB, long strideC)
{
    const int bz = blockIdx.z;
    A    += (long)bz * strideA;
    Bmat += (long)bz * strideB;
    C    += (long)bz * strideC;

    const int brow = blockIdx.y;
    const int bcol = blockIdx.x;

    if (CSKIP) {
        // block rows [brow*BM, brow*BM+BM-1], cols [bcol*BN, ...]
        // needed iff some j <= i exists: brow*BM+BM-1 >= bcol*BN
        if (brow * BM + BM - 1 < bcol * BN) return;
    }

    __shared__ float As[BK][BM];
    __shared__ float Bs[BK][BN];

    const int tid = threadIdx.x;
    const int tr  = tid / (BN / TN);   // 0..15
    const int tc  = tid % (BN / TN);   // 0..15

    float acc[TM][TN] = {};

    for (int k0 = 0; k0 < K; k0 += BK) {
        // ---- load A tile: BM x BK = 128x16 floats = 512 float4 ----
        #pragma unroll
        for (int i = 0; i < 2; i++) {
            int idx = tid + i * NTHREADS;        // 0..511
            int ar  = idx >> 2;                  // row in tile 0..127
            int ak  = (idx & 3) << 2;            // k offset 0,4,8,12
            float4 v = *(const float4*)(A + (long)(brow * BM + ar) * K + k0 + ak);
            As[ak + 0][ar] = v.x;
            As[ak + 1][ar] = v.y;
            As[ak + 2][ar] = v.z;
            As[ak + 3][ar] = v.w;
        }
        // ---- load B tile into Bs[k][n] ----
        if (!TRANSB) {
            // B: [K, N]; tile BK x BN = 16x128
            #pragma unroll
            for (int i = 0; i < 2; i++) {
                int idx = tid + i * NTHREADS;    // 0..511
                int bk  = idx >> 5;              // 0..15  (32 float4 per row)
                int bn  = (idx & 31) << 2;       // 0..124
                float4 v = *(const float4*)(Bmat + (long)(k0 + bk) * N + bcol * BN + bn);
                *(float4*)&Bs[bk][bn] = v;
            }
        } else {
            // B: [N, K]; Bs[k][n] = B[bcol*BN + n][k0 + k]
            #pragma unroll
            for (int i = 0; i < 2; i++) {
                int idx = tid + i * NTHREADS;    // 0..511
                int bn  = idx >> 2;              // 0..127
                int bk  = (idx & 3) << 2;        // 0,4,8,12
                float4 v = *(const float4*)(Bmat + (long)(bcol * BN + bn) * K + k0 + bk);
                Bs[bk + 0][bn] = v.x;
                Bs[bk + 1][bn] = v.y;
                Bs[bk + 2][bn] = v.z;
                Bs[bk + 3][bn] = v.w;
            }
        }
        __syncthreads();

        // ---- micro-kernel ----
        #pragma unroll
        for (int kk = 0; kk < BK; kk++) {
            float4 a0 = *(float4*)&As[kk][tr * TM];
            float4 a1 = *(float4*)&As[kk][tr * TM + 4];
            float4 b0 = *(float4*)&Bs[kk][tc * TN];
            float4 b1 = *(float4*)&Bs[kk][tc * TN + 4];
            float a[TM] = {a0.x, a0.y, a0.z, a0.w, a1.x, a1.y, a1.z, a1.w};
            float b[TN] = {b0.x, b0.y, b0.z, b0.w, b1.x, b1.y, b1.z, b1.w};
            #pragma unroll
            for (int i = 0; i < TM; i++)
                #pragma unroll
                for (int j = 0; j < TN; j++)
                    acc[i][j] += a[i] * b[j];
        }
        __syncthreads();
    }

    // ---- store ----
    #pragma unroll
    for (int i = 0; i < TM; i++) {
        long row = (long)(brow * BM + tr * TM + i);
        #pragma unroll
        for (int j = 0; j < TN; j += 4) {
            float4 v = make_float4(acc[i][j + 0] * alpha,
                                   acc[i][j + 1] * alpha,
                                   acc[i][j + 2] * alpha,
                                   acc[i][j + 3] * alpha);
            *(float4*)(C + row * N + bcol * BN + tc * TN + j) = v;
        }
    }
}

// ---------------------------------------------------------------------------
// Causal row softmax, in place on S.
// grid: (SEQ, BATCH), block: 256 threads. Row i uses entries j in [0, i].
// Entries j > i are written as 0 so PV can be a dense GEMM.
// ---------------------------------------------------------------------------
__global__ __launch_bounds__(256)
void softmax_causal_kernel(float* __restrict__ S)
{
    const int row = blockIdx.x;
    const int b   = blockIdx.y;
    float* s = S + ((long)b * SEQ + row) * SEQ;
    const int L = row + 1;

    __shared__ float sh[32];
    const int lane = threadIdx.x & 31;
    const int warp = threadIdx.x >> 5;
    const int nwarps = blockDim.x >> 5;

    // pass 1: max
    float m = -INFINITY;
    for (int j = threadIdx.x; j < L; j += blockDim.x) m = fmaxf(m, s[j]);
    #pragma unroll
    for (int o = 16; o > 0; o >>= 1) m = fmaxf(m, __shfl_xor_sync(0xffffffffu, m, o));
    if (lane == 0) sh[warp] = m;
    __syncthreads();
    if (warp == 0) {
        float v = (lane < nwarps) ? sh[lane] : -INFINITY;
        #pragma unroll
        for (int o = 16; o > 0; o >>= 1) v = fmaxf(v, __shfl_xor_sync(0xffffffffu, v, o));
        if (lane == 0) sh[0] = v;
    }
    __syncthreads();
    m = sh[0];
    __syncthreads();

    // pass 2: exp + sum (store exp in place)
    float sum = 0.0f;
    for (int j = threadIdx.x; j < L; j += blockDim.x) {
        float e = expf(s[j] - m);
        s[j] = e;
        sum += e;
    }
    #pragma unroll
    for (int o = 16; o > 0; o >>= 1) sum += __shfl_xor_sync(0xffffffffu, sum, o);
    if (lane == 0) sh[warp] = sum;
    __syncthreads();
    if (warp == 0) {
        float v = (lane < nwarps) ? sh[lane] : 0.0f;
        #pragma unroll
        for (int o = 16; o > 0; o >>= 1) v += __shfl_xor_sync(0xffffffffu, v, o);
        if (lane == 0) sh[0] = v;
    }
    __syncthreads();
    const float inv = 1.0f / sh[0];

    // pass 3: normalize + zero the masked tail
    for (int j = threadIdx.x; j < L; j += blockDim.x) s[j] *= inv;
    for (int j = L + threadIdx.x; j < SEQ; j += blockDim.x) s[j] = 0.0f;
}

// ---------------------------------------------------------------------------
extern "C" void kernel_launch(void* const* d_in, const int* in_sizes, int n_in,
                              void* d_out, int out_size)
{
    const float* x  = (const float*)d_in[0];   // [4, 2048, 1024]
    const float* Wq = (const float*)d_in[1];   // [1024, 1024]
    const float* Wk = (const float*)d_in[2];
    const float* Wv = (const float*)d_in[3];
    // d_in[4]: causal_mask flag (known 1 for this problem)
    float* out = (float*)d_out;                // [4, 2048, 1024]

    float *Q, *K, *V, *S;
    cudaGetSymbolAddress((void**)&Q, g_Q);
    cudaGetSymbolAddress((void**)&K, g_K);
    cudaGetSymbolAddress((void**)&V, g_V);
    cudaGetSymbolAddress((void**)&S, g_S);

    const int M_qkv = BATCH * SEQ;   // 8192

    // 1) QKV projections: [8192,1024] x [1024,1024]
    {
        dim3 grid(DIM / BN, M_qkv / BM, 1);
        sgemm_kernel<false, false><<<grid, NTHREADS>>>(x, Wq, Q, M_qkv, DIM, DIM, 1.0f, 0, 0, 0);
        sgemm_kernel<false, false><<<grid, NTHREADS>>>(x, Wk, K, M_qkv, DIM, DIM, 1.0f, 0, 0, 0);
        sgemm_kernel<false, false><<<grid, NTHREADS>>>(x, Wv, V, M_qkv, DIM, DIM, 1.0f, 0, 0, 0);
    }

    // 2) S = Q K^T * (1/sqrt(dk)), per batch, causal block-skip
    {
        dim3 grid(SEQ / BN, SEQ / BM, BATCH);
        const float scale = 1.0f / sqrtf((float)DIM);
        sgemm_kernel<true, true><<<grid, NTHREADS>>>(Q, K, S, SEQ, SEQ, DIM, scale,
                                                     (long)SEQ * DIM, (long)SEQ * DIM,
                                                     (long)SEQ * SEQ);
    }

    // 3) causal softmax rows of S (in place -> P)
    {
        dim3 grid(SEQ, BATCH, 1);
        softmax_causal_kernel<<<grid, 256>>>(S);
    }

    // 4) out = P V, per batch: [2048,2048] x [2048,1024]
    {
        dim3 grid(DIM / BN, SEQ / BM, BATCH);
        sgemm_kernel<false, false><<<grid, NTHREADS>>>(S, V, out, SEQ, DIM, SEQ, 1.0f,
                                                       (long)SEQ * SEQ, (long)SEQ * DIM,
                                                       (long)SEQ * DIM);
    }
}

// round 3
// speedup vs baseline: 2.5730x; 2.5730x over previous
#include <cuda_runtime.h>
#include <cuda_bf16.h>
#include <math.h>
#include <stdint.h>

// Problem constants
#define BATCH 4
#define SEQ   2048
#define DIM   1024

// GEMM tiling
#define BM 128
#define BN 128
#define BK 32
#define NTH 256            // 8 warps: 4 (m) x 2 (n)

// smem: bf16 tiles, rows padded to 40 elems (80 B) for conflict-free ldmatrix
#define RSB      80                      // row stride bytes
#define TILE_B   (128 * RSB)             // 10240 B per tile
#define OFF_AHI  0
#define OFF_ALO  (1 * TILE_B)
#define OFF_BHI  (2 * TILE_B)
#define OFF_BLO  (3 * TILE_B)
#define STAGE_B  (4 * TILE_B)            // 40960 B
#define SMEM_TOTAL (2 * STAGE_B)         // 81920 B

// ---------------------------------------------------------------------------
// Scratch (device globals — allocation-free per harness rules)
// ---------------------------------------------------------------------------
__device__ float g_QKV[(size_t)3 * BATCH * SEQ * DIM];   // Q | K | V planes
__device__ float g_VT [(size_t)BATCH * SEQ * DIM];       // V^T per batch [DIM, SEQ]
__device__ float g_WT [(size_t)3 * DIM * DIM];           // Wq^T, Wk^T, Wv^T
__device__ float g_S  [(size_t)BATCH * SEQ * SEQ];

// ---------------------------------------------------------------------------
// helpers
// ---------------------------------------------------------------------------
__device__ __forceinline__ uint32_t smem_u32(const void* p) {
    uint32_t a;
    asm("{ .reg .u64 t; cvta.to.shared.u64 t, %1; cvt.u32.u64 %0, t; }"
        : "=r"(a) : "l"(p));
    return a;
}

#define LDSM_X4(r0, r1, r2, r3, addr) \
    asm volatile("ldmatrix.sync.aligned.m8n8.x4.shared.b16 {%0,%1,%2,%3}, [%4];" \
                 : "=r"(r0), "=r"(r1), "=r"(r2), "=r"(r3) : "r"(addr))

#define MMA_BF16(d, a, b) \
    asm volatile("mma.sync.aligned.m16n8k16.row.col.f32.bf16.bf16.f32 " \
                 "{%0,%1,%2,%3}, {%4,%5,%6,%7}, {%8,%9}, {%0,%1,%2,%3};" \
                 : "+f"((d)[0]), "+f"((d)[1]), "+f"((d)[2]), "+f"((d)[3]) \
                 : "r"((a)[0]), "r"((a)[1]), "r"((a)[2]), "r"((a)[3]), \
                   "r"((b)[0]), "r"((b)[1]))

__device__ __forceinline__ uint32_t pack_hi2(float a, float b, float& ra, float& rb) {
    __nv_bfloat162 h = __floats2bfloat162_rn(a, b);
    float2 hf = __bfloat1622float2(h);
    ra = a - hf.x;
    rb = b - hf.y;
    return *reinterpret_cast<uint32_t*>(&h);
}
__device__ __forceinline__ uint32_t pack2(float a, float b) {
    __nv_bfloat162 h = __floats2bfloat162_rn(a, b);
    return *reinterpret_cast<uint32_t*>(&h);
}

// ---------------------------------------------------------------------------
// bf16-split GEMM via mma.sync:
//   C[M,N] = alpha * A[M,K] * B[N,K]^T   (A, B row-major K-major fp32)
// CSKIP: skip output tiles fully above causal diagonal (S = QK^T).
// KLIM : restrict K chunks to k < m0+BM (PV with causally-zeroed P).
// ---------------------------------------------------------------------------
template <bool CSKIP, bool KLIM>
__global__ __launch_bounds__(NTH, 1)
void mm_bf16(const float* __restrict__ A, const float* __restrict__ B,
             float* __restrict__ C, int N, int K, float alpha,
             long sA, long sB, long sC)
{
    const int bz = blockIdx.z;
    A += (long)bz * sA;
    B += (long)bz * sB;
    C += (long)bz * sC;

    const int m0 = blockIdx.y * BM;
    const int n0 = blockIdx.x * BN;
    if (CSKIP && (m0 + BM - 1 < n0)) return;

    int nch = K / BK;
    if (KLIM) {
        int lim = (m0 + BM) / BK;
        nch = (lim < nch) ? lim : nch;
    }

    extern __shared__ char smem[];
    const uint32_t sb = smem_u32(smem);

    const int tid  = threadIdx.x;
    const int wid  = tid >> 5;
    const int lane = tid & 31;
    const int wm   = wid & 3;       // warp m block (32 rows)
    const int wn   = wid >> 2;      // warp n block (64 cols)

    // per-thread global load slots: 2 units x 8 floats (A and B each)
    const int uRow0 = tid >> 2;               // unit 0 row
    const int uK0   = (tid & 3) << 3;         // unit 0 k offset
    const int uRow1 = (tid + NTH) >> 2;
    const int uK1   = ((tid + NTH) & 3) << 3; // == uK0, but keep general

    float4 pa[4], pb[4];

    auto load_tiles = [&](int c) {
        const float* a0 = A + (long)(m0 + uRow0) * K + c * BK + uK0;
        const float* a1 = A + (long)(m0 + uRow1) * K + c * BK + uK1;
        const float* b0 = B + (long)(n0 + uRow0) * K + c * BK + uK0;
        const float* b1 = B + (long)(n0 + uRow1) * K + c * BK + uK1;
        pa[0] = *(const float4*)(a0);
        pa[1] = *(const float4*)(a0 + 4);
        pa[2] = *(const float4*)(a1);
        pa[3] = *(const float4*)(a1 + 4);
        pb[0] = *(const float4*)(b0);
        pb[1] = *(const float4*)(b0 + 4);
        pb[2] = *(const float4*)(b1);
        pb[3] = *(const float4*)(b1 + 4);
    };

    auto store_unit = [&](char* base_hi, char* base_lo, int row, int k8,
                          float4 v0, float4 v1) {
        float r0, r1, r2, r3, r4, r5, r6, r7;
        uint4 hi, lo;
        hi.x = pack_hi2(v0.x, v0.y, r0, r1);
        hi.y = pack_hi2(v0.z, v0.w, r2, r3);
        hi.z = pack_hi2(v1.x, v1.y, r4, r5);
        hi.w = pack_hi2(v1.z, v1.w, r6, r7);
        lo.x = pack2(r0, r1);
        lo.y = pack2(r2, r3);
        lo.z = pack2(r4, r5);
        lo.w = pack2(r6, r7);
        const uint32_t off = (uint32_t)(row * RSB + k8 * 2);
        *reinterpret_cast<uint4*>(base_hi + off) = hi;
        *reinterpret_cast<uint4*>(base_lo + off) = lo;
    };

    float acc[2][8][4] = {};

    load_tiles(0);

    for (int c = 0; c < nch; c++) {
        const int st = (c & 1) * STAGE_B;
        // ---- store prefetched chunk into smem (convert to bf16 hi/lo) ----
        store_unit(smem + st + OFF_AHI, smem + st + OFF_ALO, uRow0, uK0, pa[0], pa[1]);
        store_unit(smem + st + OFF_AHI, smem + st + OFF_ALO, uRow1, uK1, pa[2], pa[3]);
        store_unit(smem + st + OFF_BHI, smem + st + OFF_BLO, uRow0, uK0, pb[0], pb[1]);
        store_unit(smem + st + OFF_BHI, smem + st + OFF_BLO, uRow1, uK1, pb[2], pb[3]);
        __syncthreads();

        if (c + 1 < nch) load_tiles(c + 1);

        // ---- compute on stage st ----
        const uint32_t aH = sb + st + OFF_AHI;
        const uint32_t aL = sb + st + OFF_ALO;
        const uint32_t bH = sb + st + OFF_BHI;
        const uint32_t bL = sb + st + OFF_BLO;

        #pragma unroll
        for (int kk = 0; kk < BK; kk += 16) {
            // A fragments: 2 m16 blocks, hi + lo
            uint32_t ahi[2][4], alo[2][4];
            {
                const int arow = wm * 32 + (lane & 15);
                const int akb  = (kk + ((lane >> 4) << 3)) * 2;
                #pragma unroll
                for (int f = 0; f < 2; f++) {
                    const uint32_t addr = (uint32_t)((arow + f * 16) * RSB + akb);
                    LDSM_X4(ahi[f][0], ahi[f][1], ahi[f][2], ahi[f][3], aH + addr);
                    LDSM_X4(alo[f][0], alo[f][1], alo[f][2], alo[f][3], aL + addr);
                }
            }
            // B fragments: 8 n8 blocks (4 ldmatrix.x4 each for hi/lo)
            uint32_t bhi[8][2], blo[8][2];
            {
                const int g = lane >> 3;                   // 0..3
                const int r = lane & 7;
                const int brow0 = wn * 64 + ((g >> 1) << 3) + r;
                const int bkb   = (kk + ((g & 1) << 3)) * 2;
                #pragma unroll
                for (int p = 0; p < 4; p++) {
                    const uint32_t addr = (uint32_t)((brow0 + p * 16) * RSB + bkb);
                    LDSM_X4(bhi[2 * p][0], bhi[2 * p][1],
                            bhi[2 * p + 1][0], bhi[2 * p + 1][1], bH + addr);
                    LDSM_X4(blo[2 * p][0], blo[2 * p][1],
                            blo[2 * p + 1][0], blo[2 * p + 1][1], bL + addr);
                }
            }
            // 3-term split MMAs
            #pragma unroll
            for (int f = 0; f < 2; f++) {
                #pragma unroll
                for (int n = 0; n < 8; n++) {
                    MMA_BF16(acc[f][n], ahi[f], bhi[n]);
                    MMA_BF16(acc[f][n], ahi[f], blo[n]);
                    MMA_BF16(acc[f][n], alo[f], bhi[n]);
                }
            }
        }
        __syncthreads();
    }

    // ---- epilogue ----
    #pragma unroll
    for (int f = 0; f < 2; f++) {
        const long r0 = (long)m0 + wm * 32 + f * 16 + (lane >> 2);
        #pragma unroll
        for (int n = 0; n < 8; n++) {
            const long col = (long)n0 + wn * 64 + n * 8 + (lane & 3) * 2;
            float2 lo = make_float2(acc[f][n][0] * alpha, acc[f][n][1] * alpha);
            float2 hi = make_float2(acc[f][n][2] * alpha, acc[f][n][3] * alpha);
            *(float2*)(C + r0 * N + col)       = lo;
            *(float2*)(C + (r0 + 8) * N + col) = hi;
        }
    }
}

// ---------------------------------------------------------------------------
// fp32 transpose: out[C,R] = in[R,C]^T  (32x32 tiles, block 32x8)
// ---------------------------------------------------------------------------
__global__ void transpose_k(const float* __restrict__ in, float* __restrict__ out,
                            int R, int C, long sIn, long sOut)
{
    __shared__ float t[32][33];
    const long b = blockIdx.z;
    in  += b * sIn;
    out += b * sOut;
    const int c0 = blockIdx.x * 32, r0 = blockIdx.y * 32;
    #pragma unroll
    for (int i = threadIdx.y; i < 32; i += 8)
        t[i][threadIdx.x] = in[(long)(r0 + i) * C + c0 + threadIdx.x];
    __syncthreads();
    #pragma unroll
    for (int i = threadIdx.y; i < 32; i += 8)
        out[(long)(c0 + i) * R + r0 + threadIdx.x] = t[threadIdx.x][i];
}

// ---------------------------------------------------------------------------
// Causal row softmax, in place on S (zeros the masked tail).
// ---------------------------------------------------------------------------
__global__ __launch_bounds__(256)
void softmax_causal_kernel(float* __restrict__ S)
{
    const int row = blockIdx.x;
    const int b   = blockIdx.y;
    float* s = S + ((long)b * SEQ + row) * SEQ;
    const int L = row + 1;

    __shared__ float sh[32];
    const int lane = threadIdx.x & 31;
    const int warp = threadIdx.x >> 5;
    const int nwarps = blockDim.x >> 5;

    float m = -INFINITY;
    for (int j = threadIdx.x; j < L; j += blockDim.x) m = fmaxf(m, s[j]);
    #pragma unroll
    for (int o = 16; o > 0; o >>= 1) m = fmaxf(m, __shfl_xor_sync(0xffffffffu, m, o));
    if (lane == 0) sh[warp] = m;
    __syncthreads();
    if (warp == 0) {
        float v = (lane < nwarps) ? sh[lane] : -INFINITY;
        #pragma unroll
        for (int o = 16; o > 0; o >>= 1) v = fmaxf(v, __shfl_xor_sync(0xffffffffu, v, o));
        if (lane == 0) sh[0] = v;
    }
    __syncthreads();
    m = sh[0];
    __syncthreads();

    float sum = 0.0f;
    for (int j = threadIdx.x; j < L; j += blockDim.x) {
        float e = expf(s[j] - m);
        s[j] = e;
        sum += e;
    }
    #pragma unroll
    for (int o = 16; o > 0; o >>= 1) sum += __shfl_xor_sync(0xffffffffu, sum, o);
    if (lane == 0) sh[warp] = sum;
    __syncthreads();
    if (warp == 0) {
        float v = (lane < nwarps) ? sh[lane] : 0.0f;
        #pragma unroll
        for (int o = 16; o > 0; o >>= 1) v += __shfl_xor_sync(0xffffffffu, v, o);
        if (lane == 0) sh[0] = v;
    }
    __syncthreads();
    const float inv = 1.0f / sh[0];

    for (int j = threadIdx.x; j < L; j += blockDim.x) s[j] *= inv;
    for (int j = L + threadIdx.x; j < SEQ; j += blockDim.x) s[j] = 0.0f;
}

// ---------------------------------------------------------------------------
extern "C" void kernel_launch(void* const* d_in, const int* in_sizes, int n_in,
                              void* d_out, int out_size)
{
    const float* x  = (const float*)d_in[0];   // [4, 2048, 1024]
    const float* Wq = (const float*)d_in[1];   // [1024, 1024] (in, out)
    const float* Wk = (const float*)d_in[2];
    const float* Wv = (const float*)d_in[3];
    float* out = (float*)d_out;                // [4, 2048, 1024]

    float *QKV, *VT, *WT, *S;
    cudaGetSymbolAddress((void**)&QKV, g_QKV);
    cudaGetSymbolAddress((void**)&VT,  g_VT);
    cudaGetSymbolAddress((void**)&WT,  g_WT);
    cudaGetSymbolAddress((void**)&S,   g_S);

    cudaFuncSetAttribute(mm_bf16<false, false>,
                         cudaFuncAttributeMaxDynamicSharedMemorySize, SMEM_TOTAL);
    cudaFuncSetAttribute(mm_bf16<true, false>,
                         cudaFuncAttributeMaxDynamicSharedMemorySize, SMEM_TOTAL);
    cudaFuncSetAttribute(mm_bf16<false, true>,
                         cudaFuncAttributeMaxDynamicSharedMemorySize, SMEM_TOTAL);

    const long PLANE = (long)BATCH * SEQ * DIM;

    // 0) W transposes: WT[z] = W_z^T  ([out, in] row-major)
    {
        dim3 blk(32, 8), grd(DIM / 32, DIM / 32, 1);
        transpose_k<<<grd, blk>>>(Wq, WT + 0 * (long)DIM * DIM, DIM, DIM, 0, 0);
        transpose_k<<<grd, blk>>>(Wk, WT + 1 * (long)DIM * DIM, DIM, DIM, 0, 0);
        transpose_k<<<grd, blk>>>(Wv, WT + 2 * (long)DIM * DIM, DIM, DIM, 0, 0);
    }

    // 1) QKV projections: z = 0,1,2 over {Wq^T, Wk^T, Wv^T}
    {
        dim3 grd(DIM / BN, (BATCH * SEQ) / BM, 3);
        mm_bf16<false, false><<<grd, NTH, SMEM_TOTAL>>>(
            x, WT, QKV, DIM, DIM, 1.0f, 0, (long)DIM * DIM, PLANE);
    }

    // 2) V^T per batch: [2048,1024] -> [1024,2048]
    {
        dim3 blk(32, 8), grd(DIM / 32, SEQ / 32, BATCH);
        transpose_k<<<grd, blk>>>(QKV + 2 * PLANE, VT, SEQ, DIM,
                                  (long)SEQ * DIM, (long)SEQ * DIM);
    }

    // 3) S = Q K^T * scale (causal block-skip)
    {
        dim3 grd(SEQ / BN, SEQ / BM, BATCH);
        mm_bf16<true, false><<<grd, NTH, SMEM_TOTAL>>>(
            QKV, QKV + PLANE, S, SEQ, DIM, 1.0f / sqrtf((float)DIM),
            (long)SEQ * DIM, (long)SEQ * DIM, (long)SEQ * SEQ);
    }

    // 4) causal softmax (in place)
    {
        dim3 grd(SEQ, BATCH, 1);
        softmax_causal_kernel<<<grd, 256>>>(S);
    }

    // 5) out = P V  (B = V^T is [DIM, SEQ] K-major); K-chunks causally limited
    {
        dim3 grd(DIM / BN, SEQ / BM, BATCH);
        mm_bf16<false, true><<<grd, NTH, SMEM_TOTAL>>>(
            S, VT, out, DIM, SEQ, 1.0f,
            (long)SEQ * SEQ, (long)SEQ * DIM, (long)SEQ * DIM);
    }
}

// round 4
// speedup vs baseline: 2.7604x; 1.0728x over previous
#include <cuda_runtime.h>
#include <cuda_bf16.h>
#include <math.h>
#include <stdint.h>

// Problem constants
#define BATCH 4
#define SEQ   2048
#define DIM   1024

// GEMM tiling
#define BM 128
#define BN 128
#define BK 32
#define NTH 256            // 8 warps: 4 (m) x 2 (n)

// smem: bf16 tiles, rows padded to 40 elems (80 B) for conflict-free ldmatrix
#define RSB      80
#define TILE_B   (128 * RSB)             // 10240 B per plane tile
#define OFF_AHI  0
#define OFF_ALO  (1 * TILE_B)
#define OFF_BHI  (2 * TILE_B)
#define OFF_BLO  (3 * TILE_B)
#define STAGE_B  (4 * TILE_B)            // 40960 B
#define SMEM_TOTAL (2 * STAGE_B)         // 81920 B -> 2 CTAs/SM

typedef __nv_bfloat16 bf16;

// ---------------------------------------------------------------------------
// Scratch (device globals — allocation-free per harness rules)
// ---------------------------------------------------------------------------
#define PLANE  ((long)BATCH * SEQ * DIM)     // 8M elems
__device__ bf16  g_xhi[PLANE],  g_xlo[PLANE];
__device__ bf16  g_Whi[3 * DIM * DIM], g_Wlo[3 * DIM * DIM];
__device__ bf16  g_QKhi[2 * PLANE], g_QKlo[2 * PLANE];   // Q plane | K plane
__device__ float g_V[PLANE];
__device__ bf16  g_VThi[PLANE], g_VTlo[PLANE];           // per batch [DIM, SEQ]
__device__ float g_S[(size_t)BATCH * SEQ * SEQ];
__device__ bf16  g_Phi[(size_t)BATCH * SEQ * SEQ], g_Plo[(size_t)BATCH * SEQ * SEQ];

// ---------------------------------------------------------------------------
// helpers
// ---------------------------------------------------------------------------
__device__ __forceinline__ uint32_t smem_u32(const void* p) {
    uint32_t a;
    asm("{ .reg .u64 t; cvta.to.shared.u64 t, %1; cvt.u32.u64 %0, t; }"
        : "=r"(a) : "l"(p));
    return a;
}

__device__ __forceinline__ void cpa16(uint32_t dst, const void* src) {
    asm volatile("cp.async.cg.shared.global [%0], [%1], 16;"
                 :: "r"(dst), "l"(src) : "memory");
}
#define CP_COMMIT() asm volatile("cp.async.commit_group;" ::: "memory")
#define CP_WAIT(n)  asm volatile("cp.async.wait_group %0;" :: "n"(n) : "memory")

#define LDSM_X4(r0, r1, r2, r3, addr) \
    asm volatile("ldmatrix.sync.aligned.m8n8.x4.shared.b16 {%0,%1,%2,%3}, [%4];" \
                 : "=r"(r0), "=r"(r1), "=r"(r2), "=r"(r3) : "r"(addr))

#define MMA_BF16(d, a, b) \
    asm volatile("mma.sync.aligned.m16n8k16.row.col.f32.bf16.bf16.f32 " \
                 "{%0,%1,%2,%3}, {%4,%5,%6,%7}, {%8,%9}, {%0,%1,%2,%3};" \
                 : "+f"((d)[0]), "+f"((d)[1]), "+f"((d)[2]), "+f"((d)[3]) \
                 : "r"((a)[0]), "r"((a)[1]), "r"((a)[2]), "r"((a)[3]), \
                   "r"((b)[0]), "r"((b)[1]))

// split 2 floats -> packed bf16x2 (hi) and packed bf16x2 (lo residual)
__device__ __forceinline__ void split_pack2(float a, float b,
                                            uint32_t& hi, uint32_t& lo) {
    __nv_bfloat162 h = __floats2bfloat162_rn(a, b);
    float2 hf = __bfloat1622float2(h);
    __nv_bfloat162 l = __floats2bfloat162_rn(a - hf.x, b - hf.y);
    hi = *reinterpret_cast<uint32_t*>(&h);
    lo = *reinterpret_cast<uint32_t*>(&l);
}

// ---------------------------------------------------------------------------
// bf16 split GEMM (pre-split inputs):
//   C[M,N] = alpha * (Ahi+Alo)[M,K] * (Bhi+Blo)[N,K]^T   (lo*lo dropped)
// EPI 0: C fp32;  EPI 1: C written as hi/lo bf16 planes.
// CSKIP: skip tiles above causal diagonal. KLIM: K chunks < m0+BM.
// ---------------------------------------------------------------------------
template <bool CSKIP, bool KLIM, int EPI>
__global__ __launch_bounds__(NTH, 2)
void mm_s(const bf16* __restrict__ Ahi, const bf16* __restrict__ Alo,
          const bf16* __restrict__ Bhi, const bf16* __restrict__ Blo,
          float* __restrict__ C, bf16* __restrict__ Chi, bf16* __restrict__ Clo,
          int N, int K, float alpha, long sA, long sB, long sC)
{
    const int bz = blockIdx.z;
    Ahi += (long)bz * sA;  Alo += (long)bz * sA;
    Bhi += (long)bz * sB;  Blo += (long)bz * sB;

    const int m0 = blockIdx.y * BM;
    const int n0 = blockIdx.x * BN;
    if (CSKIP && (m0 + BM - 1 < n0)) return;

    int nch = K / BK;
    if (KLIM) {
        int lim = (m0 + BM) / BK;
        nch = (lim < nch) ? lim : nch;
    }

    extern __shared__ char smem[];
    const uint32_t sb = smem_u32(smem);

    const int tid  = threadIdx.x;
    const int wid  = tid >> 5;
    const int lane = tid & 31;
    const int wm   = wid & 3;       // warp m block (32 rows)
    const int wn   = wid >> 2;      // warp n block (64 cols)

    // cp.async slots: 512 16B-chunks per plane tile; 2 per thread
    const int ch0 = tid * 2;
    const int r0c = ch0 >> 2,      o0 = (ch0 & 3);
    const int r1c = (ch0 + 1) >> 2, o1 = ((ch0 + 1) & 3);

    auto stage_load = [&](int c, int buf) {
        const uint32_t st = sb + buf * STAGE_B;
        const long ga0 = (long)(m0 + r0c) * K + c * BK + o0 * 8;
        const long ga1 = (long)(m0 + r1c) * K + c * BK + o1 * 8;
        const long gb0 = (long)(n0 + r0c) * K + c * BK + o0 * 8;
        const long gb1 = (long)(n0 + r1c) * K + c * BK + o1 * 8;
        const uint32_t d0 = r0c * RSB + o0 * 16;
        const uint32_t d1 = r1c * RSB + o1 * 16;
        cpa16(st + OFF_AHI + d0, Ahi + ga0);
        cpa16(st + OFF_AHI + d1, Ahi + ga1);
        cpa16(st + OFF_ALO + d0, Alo + ga0);
        cpa16(st + OFF_ALO + d1, Alo + ga1);
        cpa16(st + OFF_BHI + d0, Bhi + gb0);
        cpa16(st + OFF_BHI + d1, Bhi + gb1);
        cpa16(st + OFF_BLO + d0, Blo + gb0);
        cpa16(st + OFF_BLO + d1, Blo + gb1);
        CP_COMMIT();
    };

    float acc[2][8][4] = {};

    stage_load(0, 0);

    for (int c = 0; c < nch; c++) {
        const int buf = c & 1;
        if (c + 1 < nch) { stage_load(c + 1, buf ^ 1); CP_WAIT(1); }
        else             { CP_WAIT(0); }
        __syncthreads();

        const uint32_t aH = sb + buf * STAGE_B + OFF_AHI;
        const uint32_t aL = sb + buf * STAGE_B + OFF_ALO;
        const uint32_t bH = sb + buf * STAGE_B + OFF_BHI;
        const uint32_t bL = sb + buf * STAGE_B + OFF_BLO;

        #pragma unroll
        for (int kk = 0; kk < BK; kk += 16) {
            uint32_t ahi[2][4], alo[2][4];
            {
                const int arow = wm * 32 + (lane & 15);
                const int akb  = (kk + ((lane >> 4) << 3)) * 2;
                #pragma unroll
                for (int f = 0; f < 2; f++) {
                    const uint32_t addr = (uint32_t)((arow + f * 16) * RSB + akb);
                    LDSM_X4(ahi[f][0], ahi[f][1], ahi[f][2], ahi[f][3], aH + addr);
                    LDSM_X4(alo[f][0], alo[f][1], alo[f][2], alo[f][3], aL + addr);
                }
            }
            const int g = lane >> 3;
            const int r = lane & 7;
            const int brow0 = wn * 64 + ((g >> 1) << 3) + r;
            const int bkb   = (kk + ((g & 1) << 3)) * 2;
            #pragma unroll
            for (int p = 0; p < 4; p++) {
                uint32_t bhi[2][2], blo[2][2];
                const uint32_t addr = (uint32_t)((brow0 + p * 16) * RSB + bkb);
                LDSM_X4(bhi[0][0], bhi[0][1], bhi[1][0], bhi[1][1], bH + addr);
                LDSM_X4(blo[0][0], blo[0][1], blo[1][0], blo[1][1], bL + addr);
                #pragma unroll
                for (int f = 0; f < 2; f++) {
                    #pragma unroll
                    for (int q = 0; q < 2; q++) {
                        const int n = 2 * p + q;
                        MMA_BF16(acc[f][n], ahi[f], bhi[q]);
                        MMA_BF16(acc[f][n], ahi[f], blo[q]);
                        MMA_BF16(acc[f][n], alo[f], bhi[q]);
                    }
                }
            }
        }
        __syncthreads();
    }

    // ---- epilogue ----
    #pragma unroll
    for (int f = 0; f < 2; f++) {
        const long r0 = (long)m0 + wm * 32 + f * 16 + (lane >> 2);
        #pragma unroll
        for (int n = 0; n < 8; n++) {
            const long col = (long)n0 + wn * 64 + n * 8 + (lane & 3) * 2;
            float v0 = acc[f][n][0] * alpha, v1 = acc[f][n][1] * alpha;
            float v2 = acc[f][n][2] * alpha, v3 = acc[f][n][3] * alpha;
            if (EPI == 0) {
                *(float2*)(C + ((long)bz * sC) + r0 * N + col)       = make_float2(v0, v1);
                *(float2*)(C + ((long)bz * sC) + (r0 + 8) * N + col) = make_float2(v2, v3);
            } else {
                uint32_t h0, l0, h1, l1;
                split_pack2(v0, v1, h0, l0);
                split_pack2(v2, v3, h1, l1);
                bf16* chp = Chi + (long)bz * sC;
                bf16* clp = Clo + (long)bz * sC;
                *(uint32_t*)(chp + r0 * N + col)       = h0;
                *(uint32_t*)(clp + r0 * N + col)       = l0;
                *(uint32_t*)(chp + (r0 + 8) * N + col) = h1;
                *(uint32_t*)(clp + (r0 + 8) * N + col) = l1;
            }
        }
    }
}

// ---------------------------------------------------------------------------
// elementwise split: fp32 -> bf16 hi/lo planes (float4 per thread)
// ---------------------------------------------------------------------------
__global__ __launch_bounds__(256)
void split_f32(const float* __restrict__ in, bf16* __restrict__ hi,
               bf16* __restrict__ lo, long n4)
{
    long i = (long)blockIdx.x * blockDim.x + threadIdx.x;
    if (i >= n4) return;
    float4 v = ((const float4*)in)[i];
    uint2 h, l;
    split_pack2(v.x, v.y, h.x, l.x);
    split_pack2(v.z, v.w, h.y, l.y);
    ((uint2*)hi)[i] = h;
    ((uint2*)lo)[i] = l;
}

// ---------------------------------------------------------------------------
// transpose + split: in fp32 [R,C] -> out hi/lo bf16 [C,R]
// ---------------------------------------------------------------------------
__global__ void transpose_split(const float* __restrict__ in,
                                bf16* __restrict__ ohi, bf16* __restrict__ olo,
                                int R, int C, long sIn, long sOut)
{
    __shared__ float t[32][33];
    const long b = blockIdx.z;
    in  += b * sIn;
    ohi += b * sOut;
    olo += b * sOut;
    const int c0 = blockIdx.x * 32, r0 = blockIdx.y * 32;
    #pragma unroll
    for (int i = threadIdx.y; i < 32; i += 8)
        t[i][threadIdx.x] = in[(long)(r0 + i) * C + c0 + threadIdx.x];
    __syncthreads();
    #pragma unroll
    for (int i = threadIdx.y; i < 32; i += 8) {
        float v = t[threadIdx.x][i];
        bf16 h = __float2bfloat16(v);
        bf16 l = __float2bfloat16(v - __bfloat162float(h));
        ohi[(long)(c0 + i) * R + r0 + threadIdx.x] = h;
        olo[(long)(c0 + i) * R + r0 + threadIdx.x] = l;
    }
}

// ---------------------------------------------------------------------------
// Causal row softmax: S fp32 (in-place exp) -> P hi/lo bf16 planes + zero tail
// ---------------------------------------------------------------------------
__global__ __launch_bounds__(256)
void softmax_split(float* __restrict__ S, bf16* __restrict__ Phi,
                   bf16* __restrict__ Plo)
{
    const int row = blockIdx.x;
    const int b   = blockIdx.y;
    const long base = ((long)b * SEQ + row) * SEQ;
    float* s = S + base;
    bf16* ph = Phi + base;
    bf16* pl = Plo + base;
    const int L = row + 1;

    __shared__ float sh[32];
    const int lane = threadIdx.x & 31;
    const int warp = threadIdx.x >> 5;
    const int nwarps = blockDim.x >> 5;

    float m = -INFINITY;
    for (int j = threadIdx.x; j < L; j += blockDim.x) m = fmaxf(m, s[j]);
    #pragma unroll
    for (int o = 16; o > 0; o >>= 1) m = fmaxf(m, __shfl_xor_sync(0xffffffffu, m, o));
    if (lane == 0) sh[warp] = m;
    __syncthreads();
    if (warp == 0) {
        float v = (lane < nwarps) ? sh[lane] : -INFINITY;
        #pragma unroll
        for (int o = 16; o > 0; o >>= 1) v = fmaxf(v, __shfl_xor_sync(0xffffffffu, v, o));
        if (lane == 0) sh[0] = v;
    }
    __syncthreads();
    m = sh[0];
    __syncthreads();

    float sum = 0.0f;
    for (int j = threadIdx.x; j < L; j += blockDim.x) {
        float e = __expf(s[j] - m);
        s[j] = e;
        sum += e;
    }
    #pragma unroll
    for (int o = 16; o > 0; o >>= 1) sum += __shfl_xor_sync(0xffffffffu, sum, o);
    if (lane == 0) sh[warp] = sum;
    __syncthreads();
    if (warp == 0) {
        float v = (lane < nwarps) ? sh[lane] : 0.0f;
        #pragma unroll
        for (int o = 16; o > 0; o >>= 1) v += __shfl_xor_sync(0xffffffffu, v, o);
        if (lane == 0) sh[0] = v;
    }
    __syncthreads();
    const float inv = 1.0f / sh[0];

    for (int j = threadIdx.x; j < L; j += blockDim.x) {
        float p = s[j] * inv;
        bf16 h = __float2bfloat16(p);
        bf16 l = __float2bfloat16(p - __bfloat162float(h));
        ph[j] = h;
        pl[j] = l;
    }
    const bf16 z = __float2bfloat16(0.0f);
    for (int j = L + threadIdx.x; j < SEQ; j += blockDim.x) { ph[j] = z; pl[j] = z; }
}

// ---------------------------------------------------------------------------
extern "C" void kernel_launch(void* const* d_in, const int* in_sizes, int n_in,
                              void* d_out, int out_size)
{
    const float* x  = (const float*)d_in[0];
    const float* Wq = (const float*)d_in[1];
    const float* Wk = (const float*)d_in[2];
    const float* Wv = (const float*)d_in[3];
    float* out = (float*)d_out;

    bf16 *xhi, *xlo, *Whi, *Wlo, *QKhi, *QKlo, *VThi, *VTlo, *Phi, *Plo;
    float *V, *S;
    cudaGetSymbolAddress((void**)&xhi,  g_xhi);
    cudaGetSymbolAddress((void**)&xlo,  g_xlo);
    cudaGetSymbolAddress((void**)&Whi,  g_Whi);
    cudaGetSymbolAddress((void**)&Wlo,  g_Wlo);
    cudaGetSymbolAddress((void**)&QKhi, g_QKhi);
    cudaGetSymbolAddress((void**)&QKlo, g_QKlo);
    cudaGetSymbolAddress((void**)&V,    g_V);
    cudaGetSymbolAddress((void**)&VThi, g_VThi);
    cudaGetSymbolAddress((void**)&VTlo, g_VTlo);
    cudaGetSymbolAddress((void**)&S,    g_S);
    cudaGetSymbolAddress((void**)&Phi,  g_Phi);
    cudaGetSymbolAddress((void**)&Plo,  g_Plo);

    cudaFuncSetAttribute((const void*)mm_s<false, false, 1>,
                         cudaFuncAttributeMaxDynamicSharedMemorySize, SMEM_TOTAL);
    cudaFuncSetAttribute((const void*)mm_s<false, false, 0>,
                         cudaFuncAttributeMaxDynamicSharedMemorySize, SMEM_TOTAL);
    cudaFuncSetAttribute((const void*)mm_s<true, false, 0>,
                         cudaFuncAttributeMaxDynamicSharedMemorySize, SMEM_TOTAL);
    cudaFuncSetAttribute((const void*)mm_s<false, true, 0>,
                         cudaFuncAttributeMaxDynamicSharedMemorySize, SMEM_TOTAL);

    const long WP = (long)DIM * DIM;

    // 0) split x; transpose+split W
    split_f32<<<(unsigned)((PLANE / 4 + 255) / 256), 256>>>(x, xhi, xlo, PLANE / 4);
    {
        dim3 blk(32, 8), grd(DIM / 32, DIM / 32, 1);
        transpose_split<<<grd, blk>>>(Wq, Whi + 0 * WP, Wlo + 0 * WP, DIM, DIM, 0, 0);
        transpose_split<<<grd, blk>>>(Wk, Whi + 1 * WP, Wlo + 1 * WP, DIM, DIM, 0, 0);
        transpose_split<<<grd, blk>>>(Wv, Whi + 2 * WP, Wlo + 2 * WP, DIM, DIM, 0, 0);
    }

    // 1a) Q,K projections -> split planes
    {
        dim3 grd(DIM / BN, (BATCH * SEQ) / BM, 2);
        mm_s<false, false, 1><<<grd, NTH, SMEM_TOTAL>>>(
            xhi, xlo, Whi, Wlo, nullptr, QKhi, QKlo,
            DIM, DIM, 1.0f, 0, WP, PLANE);
    }
    // 1b) V projection -> fp32
    {
        dim3 grd(DIM / BN, (BATCH * SEQ) / BM, 1);
        mm_s<false, false, 0><<<grd, NTH, SMEM_TOTAL>>>(
            xhi, xlo, Whi + 2 * WP, Wlo + 2 * WP, V, nullptr, nullptr,
            DIM, DIM, 1.0f, 0, 0, 0);
    }

    // 2) V^T per batch -> split planes [DIM, SEQ]
    {
        dim3 blk(32, 8), grd(DIM / 32, SEQ / 32, BATCH);
        transpose_split<<<grd, blk>>>(V, VThi, VTlo, SEQ, DIM,
                                      (long)SEQ * DIM, (long)SEQ * DIM);
    }

    // 3) S = Q K^T * scale (causal block-skip), fp32 out
    {
        dim3 grd(SEQ / BN, SEQ / BM, BATCH);
        mm_s<true, false, 0><<<grd, NTH, SMEM_TOTAL>>>(
            QKhi, QKlo, QKhi + PLANE, QKlo + PLANE, S, nullptr, nullptr,
            SEQ, DIM, 1.0f / sqrtf((float)DIM),
            (long)SEQ * DIM, (long)SEQ * DIM, (long)SEQ * SEQ);
    }

    // 4) softmax -> P split planes (+ zero tail)
    {
        dim3 grd(SEQ, BATCH, 1);
        softmax_split<<<grd, 256>>>(S, Phi, Plo);
    }

    // 5) out = P V (K-chunks causally limited), fp32 out
    {
        dim3 grd(DIM / BN, SEQ / BM, BATCH);
        mm_s<false, true, 0><<<grd, NTH, SMEM_TOTAL>>>(
            Phi, Plo, VThi, VTlo, out, nullptr, nullptr,
            DIM, SEQ, 1.0f,
            (long)SEQ * SEQ, (long)SEQ * DIM, (long)SEQ * DIM);
    }
}